// round 3
// baseline (speedup 1.0000x reference)
#include <cuda_runtime.h>
#include <cstdint>
#include <math.h>

// Problem dims
#define B_   64
#define T_   512
#define I_   256
#define H_   1024
#define F_   11
#define BT   (B_ * T_)      // 32768
#define G4   (4 * H_)       // 4096

// Output layout (concat of reference return tuple, row-major each)
#define OUT_STATE_OFF  0
#define OUT_REWARD_OFF (BT * F_)                 // 360448
#define OUT_HT_OFF     (OUT_REWARD_OFF + BT)     // 393216
#define OUT_CT_OFF     (OUT_HT_OFF + B_ * H_)    // 458752

// ---------------------------------------------------------------------------
// Scratch (static device globals — no allocation allowed)
// ---------------------------------------------------------------------------
__device__ float g_Z[BT * G4];        // 512 MB: x @ W_ih^T + (b_ih + b_hh)
__device__ float g_r[BT * H_];        // 128 MB: LSTM hidden states per step
__device__ float g_sh[BT * H_];       // 128 MB: shared layer output
__device__ float g_proj[BT * 16];     // 2 MB: [logit_s, logit_r, proj_state(11), proj_r, pad, pad]
__device__ float g_h[2][B_ * H_];     // double-buffered h
__device__ float g_c[B_ * H_];        // cell state
__device__ unsigned g_bar_count;
__device__ volatile unsigned g_bar_gen;

// ---------------------------------------------------------------------------
// Software grid barrier (all blocks resident: grid <= 148 SMs)
// ---------------------------------------------------------------------------
__device__ __forceinline__ void grid_barrier() {
    __threadfence();
    __syncthreads();
    if (threadIdx.x == 0) {
        unsigned gen = g_bar_gen;
        if (atomicAdd(&g_bar_count, 1u) == gridDim.x - 1) {
            g_bar_count = 0;
            __threadfence();
            g_bar_gen = gen + 1;
        } else {
            while (g_bar_gen == gen) { }
        }
    }
    __syncthreads();
    __threadfence();
}

__global__ void init_bar_kernel() {
    g_bar_count = 0;
    g_bar_gen = 0;
}

// ---------------------------------------------------------------------------
// SGEMM: C[M,N] = A[M,K] * W[N,K]^T + bias1[n] + bias2[n]
// BM=BN=128, BK=16, 256 threads, 8x8 microtile. M,N divisible by 128, K by 16.
// ---------------------------------------------------------------------------
__global__ __launch_bounds__(256) void sgemm_tn(
    const float* __restrict__ A, const float* __restrict__ W,
    const float* __restrict__ bias1, const float* __restrict__ bias2,
    float* __restrict__ C, int M, int N, int K)
{
    __shared__ float As[16][132];
    __shared__ float Bs[16][132];
    const int tid = threadIdx.x;
    const int m0 = blockIdx.y * 128;
    const int n0 = blockIdx.x * 128;
    const int ty = tid >> 4, tx = tid & 15;     // compute: 8 rows (m), 8 cols (n)
    const int lr = tid >> 2, lc = tid & 3;      // load: 64 rows/pass, 4 float4 per row

    float acc[8][8];
#pragma unroll
    for (int i = 0; i < 8; i++)
#pragma unroll
        for (int j = 0; j < 8; j++) acc[i][j] = 0.f;

    for (int k0 = 0; k0 < K; k0 += 16) {
#pragma unroll
        for (int p = 0; p < 2; p++) {
            const int r = lr + p * 64;
            const float4 va = *reinterpret_cast<const float4*>(
                A + (size_t)(m0 + r) * K + k0 + lc * 4);
            As[lc * 4 + 0][r] = va.x; As[lc * 4 + 1][r] = va.y;
            As[lc * 4 + 2][r] = va.z; As[lc * 4 + 3][r] = va.w;
            const float4 vb = *reinterpret_cast<const float4*>(
                W + (size_t)(n0 + r) * K + k0 + lc * 4);
            Bs[lc * 4 + 0][r] = vb.x; Bs[lc * 4 + 1][r] = vb.y;
            Bs[lc * 4 + 2][r] = vb.z; Bs[lc * 4 + 3][r] = vb.w;
        }
        __syncthreads();
#pragma unroll
        for (int k = 0; k < 16; k++) {
            float a[8], b[8];
            *reinterpret_cast<float4*>(a)     = *reinterpret_cast<const float4*>(&As[k][ty * 8]);
            *reinterpret_cast<float4*>(a + 4) = *reinterpret_cast<const float4*>(&As[k][ty * 8 + 4]);
            *reinterpret_cast<float4*>(b)     = *reinterpret_cast<const float4*>(&Bs[k][tx * 8]);
            *reinterpret_cast<float4*>(b + 4) = *reinterpret_cast<const float4*>(&Bs[k][tx * 8 + 4]);
#pragma unroll
            for (int i = 0; i < 8; i++)
#pragma unroll
                for (int j = 0; j < 8; j++)
                    acc[i][j] += a[i] * b[j];
        }
        __syncthreads();
    }

#pragma unroll
    for (int i = 0; i < 8; i++) {
        const int row = m0 + ty * 8 + i;
#pragma unroll
        for (int j = 0; j < 8; j++) {
            const int col = n0 + tx * 8 + j;
            float v = acc[i][j];
            if (bias1) v += bias1[col];
            if (bias2) v += bias2[col];
            C[(size_t)row * N + col] = v;
        }
    }
}

// ---------------------------------------------------------------------------
// Persistent LSTM recurrence. 128 blocks x 256 threads, all co-resident.
// Block b owns hidden dims j in [b*8, b*8+8): computes the 32 gate rows
// (4 gates x 8 j) for all 64 batches each step, applies gates locally,
// writes h into the other buffer, then one grid barrier per step.
// ---------------------------------------------------------------------------
#define RBLK 128

__device__ __forceinline__ float sigf(float x) { return 1.f / (1.f + __expf(-x)); }

__global__ __launch_bounds__(256) void lstm_kernel(
    const float* __restrict__ Whh,
    const float* __restrict__ h0, const float* __restrict__ c0)
{
    const int tid = threadIdx.x, bid = blockIdx.x;

    // init h, c
    for (int i = bid * 256 + tid; i < B_ * H_; i += RBLK * 256) {
        g_h[0][i] = h0[i];
        g_c[i] = c0[i];
    }
    grid_barrier();

    __shared__ float As[16][68];   // h tile, transposed [k][b]
    __shared__ float Bs[16][36];   // W tile, transposed [k][n]
    __shared__ float zs[64][33];   // z tile [b][n], n = gate*8 + jj

    const int j0 = bid * 8;
    const int ty = tid >> 4, tx = tid & 15;   // compute: 4 batches x 2 n
    const int lk = tid & 15, lr = tid >> 4;   // load coords

    for (int t = 0; t < T_; t++) {
        const float* __restrict__ hcur = g_h[t & 1];
        float acc[4][2] = {{0.f,0.f},{0.f,0.f},{0.f,0.f},{0.f,0.f}};

        for (int k0 = 0; k0 < H_; k0 += 16) {
#pragma unroll
            for (int p = 0; p < 4; p++)
                As[lk][lr + p * 16] = hcur[(lr + p * 16) * H_ + k0 + lk];
#pragma unroll
            for (int p = 0; p < 2; p++) {
                const int nn = lr + p * 16;
                const int wrow = j0 + (nn & 7) + (nn >> 3) * H_;
                Bs[lk][nn] = Whh[(size_t)wrow * H_ + k0 + lk];
            }
            __syncthreads();
#pragma unroll
            for (int k = 0; k < 16; k++) {
                const float4 a = *reinterpret_cast<const float4*>(&As[k][ty * 4]);
                const float b0 = Bs[k][tx * 2], b1 = Bs[k][tx * 2 + 1];
                acc[0][0] += a.x * b0; acc[0][1] += a.x * b1;
                acc[1][0] += a.y * b0; acc[1][1] += a.y * b1;
                acc[2][0] += a.z * b0; acc[2][1] += a.z * b1;
                acc[3][0] += a.w * b0; acc[3][1] += a.w * b1;
            }
            __syncthreads();
        }

        // z = acc + Z (Z already includes both biases)
#pragma unroll
        for (int i = 0; i < 4; i++) {
            const int b = ty * 4 + i;
#pragma unroll
            for (int j = 0; j < 2; j++) {
                const int n = tx * 2 + j;
                const int col = (n >> 3) * H_ + j0 + (n & 7);
                zs[b][n] = acc[i][j] + g_Z[(size_t)(b * T_ + t) * G4 + col];
            }
        }
        __syncthreads();

        // gates: each thread handles 2 of the 512 (b, jj) entries
        float* __restrict__ hnxt = g_h[(t + 1) & 1];
#pragma unroll
        for (int r = 0; r < 2; r++) {
            const int e = tid + r * 256;
            const int b = e >> 3, jj = e & 7;
            const float zi = zs[b][jj];
            const float zf = zs[b][8 + jj];
            const float zg = zs[b][16 + jj];
            const float zo = zs[b][24 + jj];
            const int idx = b * H_ + j0 + jj;
            const float cc = sigf(zf) * g_c[idx] + sigf(zi) * tanhf(zg);
            const float hh = sigf(zo) * tanhf(cc);
            g_c[idx] = cc;
            hnxt[idx] = hh;
            g_r[(size_t)(b * T_ + t) * H_ + j0 + jj] = hh;
        }
        grid_barrier();
    }
}

// ---------------------------------------------------------------------------
// Heads: per row of g_sh, compute 14 dot products:
// [0]=logit_state, [1]=logit_reward, [2..12]=proj_state(11), [13]=proj_reward
// One warp per row.
// ---------------------------------------------------------------------------
__global__ __launch_bounds__(256) void heads_kernel(
    const float* __restrict__ w_att_s, const float* __restrict__ w_att_r,
    const float* __restrict__ W_state, const float* __restrict__ W_reward)
{
    const int warp = (blockIdx.x * blockDim.x + threadIdx.x) >> 5;
    const int lane = threadIdx.x & 31;
    if (warp >= BT) return;
    const float* rowp = g_sh + (size_t)warp * H_;

    float4 f[8];
#pragma unroll
    for (int i = 0; i < 8; i++)
        f[i] = *reinterpret_cast<const float4*>(rowp + lane * 32 + i * 4);

    float out[14];
#pragma unroll
    for (int fi = 0; fi < 14; fi++) {
        const float* wv = (fi == 0) ? w_att_s
                        : (fi == 1) ? w_att_r
                        : (fi < 13) ? (W_state + (fi - 2) * H_)
                        : W_reward;
        float s = 0.f;
#pragma unroll
        for (int i = 0; i < 8; i++) {
            const float4 w = *reinterpret_cast<const float4*>(wv + lane * 32 + i * 4);
            s += f[i].x * w.x + f[i].y * w.y + f[i].z * w.z + f[i].w * w.w;
        }
#pragma unroll
        for (int o = 16; o; o >>= 1) s += __shfl_xor_sync(0xffffffffu, s, o);
        out[fi] = s;
    }
    if (lane == 0) {
#pragma unroll
        for (int fi = 0; fi < 14; fi++)
            g_proj[(size_t)warp * 16 + fi] = out[fi];
    }
}

// ---------------------------------------------------------------------------
// Causal prefix-softmax scan over scalar logits, averaging the 12-dim
// projections. One block per batch: warp0 = state head, warp1 = reward head.
// ---------------------------------------------------------------------------
__global__ void scan_kernel(const float* __restrict__ b_state,
                            const float* __restrict__ b_reward,
                            float* __restrict__ out)
{
    const int b = blockIdx.x;
    const int w = threadIdx.x >> 5, lane = threadIdx.x & 31;
    const float* pbase = g_proj + (size_t)b * T_ * 16;

    if (w == 0) {
        float num = 0.f, den = 0.f, m = -INFINITY;
        const float bs = (lane < F_) ? b_state[lane] : 0.f;
        for (int t = 0; t < T_; t++) {
            const float* p = pbase + t * 16;
            const float l = p[0];
            const float v = (lane < F_) ? p[2 + lane] : 0.f;
            const float nm = fmaxf(m, l);
            const float sc = __expf(m - nm);
            const float e  = __expf(l - nm);
            den = den * sc + e;
            num = num * sc + e * v;
            m = nm;
            if (lane < F_)
                out[OUT_STATE_OFF + (size_t)(b * T_ + t) * F_ + lane] = num / den + bs;
        }
    } else if (w == 1) {
        float num = 0.f, den = 0.f, m = -INFINITY;
        const float br = b_reward[0];
        for (int t = 0; t < T_; t++) {
            const float* p = pbase + t * 16;
            const float l = p[1];
            const float v = p[13];
            const float nm = fmaxf(m, l);
            const float sc = __expf(m - nm);
            const float e  = __expf(l - nm);
            den = den * sc + e;
            num = num * sc + e * v;
            m = nm;
            if (lane == 0)
                out[OUT_REWARD_OFF + b * T_ + t] = num / den + br;
        }
    }
}

// ---------------------------------------------------------------------------
// Final hT / cT copy (h ended in buffer 0 after 512 steps)
// ---------------------------------------------------------------------------
__global__ void finalize_kernel(float* __restrict__ out)
{
    const int i = blockIdx.x * blockDim.x + threadIdx.x;
    if (i < B_ * H_) {
        out[OUT_HT_OFF + i] = g_h[0][i];
        out[OUT_CT_OFF + i] = g_c[i];
    }
}

// ---------------------------------------------------------------------------
// Launch
// ---------------------------------------------------------------------------
extern "C" void kernel_launch(void* const* d_in, const int* in_sizes, int n_in,
                              void* d_out, int out_size)
{
    const float* x        = (const float*)d_in[0];
    // d_in[1] = x_lengths (all == T, unused)
    const float* h0       = (const float*)d_in[2];
    const float* c0       = (const float*)d_in[3];
    const float* W_ih     = (const float*)d_in[4];
    const float* W_hh     = (const float*)d_in[5];
    const float* b_ih     = (const float*)d_in[6];
    const float* b_hh     = (const float*)d_in[7];
    const float* W_sh     = (const float*)d_in[8];
    const float* b_sh     = (const float*)d_in[9];
    const float* w_att_s  = (const float*)d_in[10];
    // d_in[11] = b_att_s (cancels in softmax)
    const float* w_att_r  = (const float*)d_in[12];
    // d_in[13] = b_att_r (cancels in softmax)
    const float* W_state  = (const float*)d_in[14];
    const float* b_state  = (const float*)d_in[15];
    const float* W_reward = (const float*)d_in[16];
    const float* b_reward = (const float*)d_in[17];
    float* out = (float*)d_out;

    float *Z, *r, *sh;
    cudaGetSymbolAddress((void**)&Z,  g_Z);
    cudaGetSymbolAddress((void**)&r,  g_r);
    cudaGetSymbolAddress((void**)&sh, g_sh);

    // Z = x @ W_ih^T + (b_ih + b_hh)   [32768, 4096]
    sgemm_tn<<<dim3(G4 / 128, BT / 128), 256>>>(x, W_ih, b_ih, b_hh, Z, BT, G4, I_);

    // LSTM recurrence (persistent, 512 steps)
    init_bar_kernel<<<1, 1>>>();
    lstm_kernel<<<RBLK, 256>>>(W_hh, h0, c0);

    // shared = r_out @ W_sh^T + b_sh   [32768, 1024]
    sgemm_tn<<<dim3(H_ / 128, BT / 128), 256>>>(r, W_sh, b_sh, nullptr, sh, BT, H_, H_);

    // 14-way projection (logits + head projections)
    heads_kernel<<<BT / 8, 256>>>(w_att_s, w_att_r, W_state, W_reward);

    // causal prefix-softmax scans -> state_out, reward_out
    scan_kernel<<<B_, 64>>>(b_state, b_reward, out);

    // hT, cT
    finalize_kernel<<<(B_ * H_ + 255) / 256, 256>>>(out);
}

// round 9
// speedup vs baseline: 2.9132x; 2.9132x over previous
#include <cuda_runtime.h>
#include <cuda_bf16.h>
#include <cstdint>
#include <math.h>

#define B_   64
#define T_   512
#define I_   256
#define H_   1024
#define F_   11
#define BT   (B_ * T_)
#define G4   (4 * H_)

#define OUT_STATE_OFF  0
#define OUT_REWARD_OFF (BT * F_)
#define OUT_HT_OFF     (OUT_REWARD_OFF + BT)
#define OUT_CT_OFF     (OUT_HT_OFF + B_ * H_)

// ---------------- scratch globals ----------------
__device__ float g_Z[BT * G4];
__device__ float g_sh[BT * H_];
__device__ float g_proj[BT * 16];
__device__ __align__(16) __nv_bfloat16 g_x_hi[BT * I_],  g_x_lo[BT * I_];
__device__ __align__(16) __nv_bfloat16 g_r_hi[BT * H_],  g_r_lo[BT * H_];
__device__ __align__(16) __nv_bfloat16 g_wih_hi[G4 * I_], g_wih_lo[G4 * I_];
__device__ __align__(16) __nv_bfloat16 g_whh_hi[G4 * H_], g_whh_lo[G4 * H_];
__device__ __align__(16) __nv_bfloat16 g_wsh_hi[H_ * H_], g_wsh_lo[H_ * H_];
__device__ __align__(16) __nv_bfloat16 g_hb_hi[2][B_ * H_], g_hb_lo[2][B_ * H_];
__device__ unsigned g_bar_count;
__device__ volatile unsigned g_bar_gen;

// ---------------- helpers ----------------
__device__ __forceinline__ uint32_t smem_u32(const void* p) {
    uint32_t a;
    asm("{ .reg .u64 t; cvta.to.shared.u64 t, %1; cvt.u32.u64 %0, t; }" : "=r"(a) : "l"(p));
    return a;
}
__device__ __forceinline__ void ldmx4(uint32_t* r, uint32_t addr) {
    asm volatile("ldmatrix.sync.aligned.m8n8.x4.shared.b16 {%0,%1,%2,%3}, [%4];"
        : "=r"(r[0]), "=r"(r[1]), "=r"(r[2]), "=r"(r[3]) : "r"(addr));
}
__device__ __forceinline__ void mma_bf16(float* d, const uint32_t* a, uint32_t b0, uint32_t b1) {
    asm volatile("mma.sync.aligned.m16n8k16.row.col.f32.bf16.bf16.f32 "
        "{%0,%1,%2,%3}, {%4,%5,%6,%7}, {%8,%9}, {%0,%1,%2,%3};"
        : "+f"(d[0]), "+f"(d[1]), "+f"(d[2]), "+f"(d[3])
        : "r"(a[0]), "r"(a[1]), "r"(a[2]), "r"(a[3]), "r"(b0), "r"(b1));
}
__device__ __forceinline__ void cp16(uint32_t dst, const void* src) {
    asm volatile("cp.async.cg.shared.global [%0], [%1], 16;" :: "r"(dst), "l"(src));
}
__device__ __forceinline__ void cp_commit() { asm volatile("cp.async.commit_group;" ::: "memory"); }
__device__ __forceinline__ void cp_wait1()  { asm volatile("cp.async.wait_group 1;" ::: "memory"); }
__device__ __forceinline__ void cp_wait0()  { asm volatile("cp.async.wait_group 0;" ::: "memory"); }

__device__ __forceinline__ float sigf(float x) { return 1.f / (1.f + __expf(-x)); }

// ---------------- grid barrier ----------------
__device__ __forceinline__ void grid_barrier() {
    __threadfence();
    __syncthreads();
    if (threadIdx.x == 0) {
        unsigned gen = g_bar_gen;
        if (atomicAdd(&g_bar_count, 1u) == gridDim.x - 1) {
            g_bar_count = 0;
            __threadfence();
            g_bar_gen = gen + 1;
        } else {
            while (g_bar_gen == gen) { }
        }
    }
    __syncthreads();
    __threadfence();
}
__global__ void init_bar_kernel() { g_bar_count = 0; g_bar_gen = 0; }

// ---------------- fp32 -> bf16 hi/lo split ----------------
__global__ __launch_bounds__(256) void split_kernel(
    const float* __restrict__ src, __nv_bfloat16* __restrict__ hi,
    __nv_bfloat16* __restrict__ lo, int n)
{
    int i = blockIdx.x * blockDim.x + threadIdx.x;
    if (i >= n) return;
    float v = src[i];
    __nv_bfloat16 h = __float2bfloat16(v);
    hi[i] = h;
    lo[i] = __float2bfloat16(v - __bfloat162float(h));
}

// ---------------- bf16 split-precision GEMM ----------------
// C[M,N] = (Ahi+Alo)[M,K] * (Whi+Wlo)[N,K]^T + bias1 + bias2  (3-term)
// 128x128 tile, BK=32, 256 threads, 8 warps (2m x 4n), warp tile m64 x n32.
#define GS_STRIDE_B 80
#define GS_ABUF     10240
#define GS_BOFF     20480
#define GS_BUF      40960
#define GEMM_SMEM   81920

__global__ __launch_bounds__(256) void hgemm_tn(
    const __nv_bfloat16* __restrict__ Ahi, const __nv_bfloat16* __restrict__ Alo,
    const __nv_bfloat16* __restrict__ Whi, const __nv_bfloat16* __restrict__ Wlo,
    const float* __restrict__ bias1, const float* __restrict__ bias2,
    float* __restrict__ C, int M, int N, int K)
{
    extern __shared__ char smg[];
    const uint32_t sb = smem_u32(smg);
    const int tid = threadIdx.x, lane = tid & 31, wid = tid >> 5;
    const int wm = wid >> 2, wn = wid & 3;
    const int m0 = blockIdx.y * 128, n0 = blockIdx.x * 128;

    float acc[4][4][4];
#pragma unroll
    for (int a = 0; a < 4; a++)
#pragma unroll
        for (int b = 0; b < 4; b++)
#pragma unroll
            for (int c = 0; c < 4; c++) acc[a][b][c] = 0.f;

    const int mrow_ld = lane & 15, kA = (lane >> 4) * 8;
    const int nrow_ld = (lane & 7) + ((lane >> 4) << 3), kB = ((lane >> 3) & 1) * 8;
    const int crow = tid >> 1, cd = tid & 1;
    const __nv_bfloat16* As = cd ? Alo : Ahi;
    const __nv_bfloat16* Bs = cd ? Wlo : Whi;
    const int nk = K / 32;

    {
        uint32_t ab = sb + cd * GS_ABUF;
        uint32_t bb = sb + GS_BOFF + cd * GS_ABUF;
#pragma unroll
        for (int s = 0; s < 4; s++) {
            cp16(ab + crow * GS_STRIDE_B + s * 16, (const char*)(As + (size_t)(m0 + crow) * K) + s * 16);
            cp16(bb + crow * GS_STRIDE_B + s * 16, (const char*)(Bs + (size_t)(n0 + crow) * K) + s * 16);
        }
        cp_commit();
    }

    for (int kk = 0; kk < nk; kk++) {
        if (kk + 1 < nk) {
            const int k0 = (kk + 1) * 32;
            uint32_t bufb = ((kk + 1) & 1) * GS_BUF;
            uint32_t ab = sb + bufb + cd * GS_ABUF;
            uint32_t bb = sb + bufb + GS_BOFF + cd * GS_ABUF;
#pragma unroll
            for (int s = 0; s < 4; s++) {
                cp16(ab + crow * GS_STRIDE_B + s * 16, (const char*)(As + (size_t)(m0 + crow) * K + k0) + s * 16);
                cp16(bb + crow * GS_STRIDE_B + s * 16, (const char*)(Bs + (size_t)(n0 + crow) * K + k0) + s * 16);
            }
            cp_commit();
            cp_wait1();
        } else {
            cp_wait0();
        }
        __syncthreads();

        const uint32_t bufb = sb + (kk & 1) * GS_BUF;
#pragma unroll
        for (int ks = 0; ks < 2; ks++) {
            uint32_t ahi[4][4], alo[4][4], bhi[2][4], blo[2][4];
#pragma unroll
            for (int mt = 0; mt < 4; mt++) {
                uint32_t ra = bufb + (wm * 64 + mt * 16 + mrow_ld) * GS_STRIDE_B + (ks * 16 + kA) * 2;
                ldmx4(ahi[mt], ra);
                ldmx4(alo[mt], ra + GS_ABUF);
            }
#pragma unroll
            for (int nb = 0; nb < 2; nb++) {
                uint32_t rb = bufb + GS_BOFF + (wn * 32 + nb * 16 + nrow_ld) * GS_STRIDE_B + (ks * 16 + kB) * 2;
                ldmx4(bhi[nb], rb);
                ldmx4(blo[nb], rb + GS_ABUF);
            }
#pragma unroll
            for (int mt = 0; mt < 4; mt++)
#pragma unroll
                for (int nt = 0; nt < 4; nt++) {
                    const int nb = nt >> 1, hf = (nt & 1) * 2;
                    mma_bf16(acc[mt][nt], ahi[mt], bhi[nb][hf], bhi[nb][hf + 1]);
                    mma_bf16(acc[mt][nt], ahi[mt], blo[nb][hf], blo[nb][hf + 1]);
                    mma_bf16(acc[mt][nt], alo[mt], bhi[nb][hf], bhi[nb][hf + 1]);
                }
        }
        __syncthreads();
    }

    const int g = lane >> 2, tq = lane & 3;
#pragma unroll
    for (int mt = 0; mt < 4; mt++)
#pragma unroll
        for (int nt = 0; nt < 4; nt++) {
            const int row = m0 + wm * 64 + mt * 16 + g;
            const int col = n0 + wn * 32 + nt * 8 + tq * 2;
            float b0 = 0.f, b1 = 0.f;
            if (bias1) { b0 += bias1[col]; b1 += bias1[col + 1]; }
            if (bias2) { b0 += bias2[col]; b1 += bias2[col + 1]; }
            C[(size_t)row * N + col]           = acc[mt][nt][0] + b0;
            C[(size_t)row * N + col + 1]       = acc[mt][nt][1] + b1;
            C[(size_t)(row + 8) * N + col]     = acc[mt][nt][2] + b0;
            C[(size_t)(row + 8) * N + col + 1] = acc[mt][nt][3] + b1;
        }
}

// ---------------- persistent HMMA LSTM recurrence ----------------
// 128 CTAs x 256 threads. CTA bid owns gate rows {g*1024 + bid*8 + jj}.
// W slice (hi+lo) resident in smem; h streamed hi/lo in 8 K-chunks of 128.
#define RNC 128
#define RS_WHI   0
#define RS_WLO   66048          // 32 rows * 2064B
#define RS_H     132096         // 2 bufs * 34816 (hi 17408 | lo 17408)
#define RS_HBUF  34816
#define RS_HLO   17408
#define RS_ZSM   201728         // 32*66*4 = 8448
#define LSTM_SMEM 210176

__global__ __launch_bounds__(256, 1) void lstm_mma_kernel(const float* __restrict__ c0,
                                                          float* __restrict__ out)
{
    extern __shared__ char sml[];
    const uint32_t sb = smem_u32(sml);
    float* zsm = reinterpret_cast<float*>(sml + RS_ZSM);

    const int tid = threadIdx.x, bid = blockIdx.x;
    const int lane = tid & 31, wid = tid >> 5;
    const int wm = wid >> 2, wn = wid & 3;
    const int j0 = bid * 8;

    // one-time: W slice (32 rows x 1024) hi+lo into smem
#pragma unroll
    for (int u = 0; u < 16; u++) {
        const int idx = tid + u * 256;               // 4096 segs
        const int r = idx >> 7, seg = idx & 127;
        const int grow = (r >> 3) * H_ + j0 + (r & 7);
        cp16(sb + RS_WHI + r * 2064 + seg * 16, (const char*)(g_whh_hi + (size_t)grow * H_) + seg * 16);
        cp16(sb + RS_WLO + r * 2064 + seg * 16, (const char*)(g_whh_lo + (size_t)grow * H_) + seg * 16);
    }
    cp_commit(); cp_wait0(); __syncthreads();

    float creg[2];
#pragma unroll
    for (int r = 0; r < 2; r++) {
        const int e = tid + r * 256;
        creg[r] = c0[(e >> 3) * H_ + j0 + (e & 7)];
    }

    const int mrow_ld = lane & 15, kA = (lane >> 4) * 8;
    const int nrow_ld = (lane & 7) + ((lane >> 4) << 3), kB = ((lane >> 3) & 1) * 8;

    for (int t = 0; t < T_; t++) {
        const char* hhi = (const char*)g_hb_hi[t & 1];
        const char* hlo = (const char*)g_hb_lo[t & 1];
        float acc[2][4] = {{0.f,0.f,0.f,0.f},{0.f,0.f,0.f,0.f}};

        // Per chunk tile: 2 dtypes x 64 rows x 256B = 2048 x 16B segments.
        // u = tid + i*256 in [0,2048): d = u>>10 (dtype), b = (u&1023)>>4, s = u&15.
        {   // prologue: chunk 0 -> buf0
#pragma unroll
            for (int i = 0; i < 8; i++) {
                const int u = tid + i * 256, d = u >> 10, v = u & 1023;
                const int b = v >> 4, s = v & 15;
                cp16(sb + RS_H + d * RS_HLO + b * 272 + s * 16,
                     (d ? hlo : hhi) + b * 2048 + s * 16);
            }
            cp_commit();
        }
        for (int c = 0; c < 8; c++) {
            if (c + 1 < 8) {
                const uint32_t hb = sb + RS_H + ((c + 1) & 1) * RS_HBUF;
#pragma unroll
                for (int i = 0; i < 8; i++) {
                    const int u = tid + i * 256, d = u >> 10, v = u & 1023;
                    const int b = v >> 4, s = v & 15;
                    cp16(hb + d * RS_HLO + b * 272 + s * 16,
                         (d ? hlo : hhi) + b * 2048 + (c + 1) * 256 + s * 16);
                }
                cp_commit();
                cp_wait1();
            } else {
                cp_wait0();
            }
            __syncthreads();

            const uint32_t hb = sb + RS_H + (c & 1) * RS_HBUF;
#pragma unroll
            for (int ks = 0; ks < 8; ks++) {
                uint32_t ahr[4], alr[4], bhr[4], blr[4];
                const uint32_t ra = sb + RS_WHI + (wm * 16 + mrow_ld) * 2064 + (c * 128 + ks * 16 + kA) * 2;
                ldmx4(ahr, ra);
                ldmx4(alr, ra + (RS_WLO - RS_WHI));
                const uint32_t rb = hb + (wn * 16 + nrow_ld) * 272 + (ks * 16 + kB) * 2;
                ldmx4(bhr, rb);
                ldmx4(blr, rb + RS_HLO);
#pragma unroll
                for (int ti = 0; ti < 2; ti++) {
                    mma_bf16(acc[ti], ahr, bhr[ti * 2], bhr[ti * 2 + 1]);
                    mma_bf16(acc[ti], ahr, blr[ti * 2], blr[ti * 2 + 1]);
                    mma_bf16(acc[ti], alr, bhr[ti * 2], bhr[ti * 2 + 1]);
                }
            }
            __syncthreads();
        }

        // frags -> zsm [row = gate*8+jj][batch]
        {
            const int g = lane >> 2, tq = lane & 3;
#pragma unroll
            for (int ti = 0; ti < 2; ti++) {
                const int col = wn * 16 + ti * 8 + tq * 2;
                zsm[(wm * 16 + g) * 66 + col]         = acc[ti][0];
                zsm[(wm * 16 + g) * 66 + col + 1]     = acc[ti][1];
                zsm[(wm * 16 + g + 8) * 66 + col]     = acc[ti][2];
                zsm[(wm * 16 + g + 8) * 66 + col + 1] = acc[ti][3];
            }
        }
        __syncthreads();

        // gates
        __nv_bfloat16* __restrict__ dsthi = g_hb_hi[(t + 1) & 1];
        __nv_bfloat16* __restrict__ dstlo = g_hb_lo[(t + 1) & 1];
#pragma unroll
        for (int r = 0; r < 2; r++) {
            const int e = tid + r * 256;
            const int b = e >> 3, jj = e & 7;
            const size_t zoff = ((size_t)(b * T_ + t)) * G4 + j0 + jj;
            const float zi = zsm[(0 * 8 + jj) * 66 + b] + g_Z[zoff];
            const float zf = zsm[(1 * 8 + jj) * 66 + b] + g_Z[zoff + H_];
            const float zg = zsm[(2 * 8 + jj) * 66 + b] + g_Z[zoff + 2 * H_];
            const float zo = zsm[(3 * 8 + jj) * 66 + b] + g_Z[zoff + 3 * H_];
            const float cc = sigf(zf) * creg[r] + sigf(zi) * tanhf(zg);
            const float hh = sigf(zo) * tanhf(cc);
            creg[r] = cc;
            const __nv_bfloat16 hi = __float2bfloat16(hh);
            const __nv_bfloat16 lo = __float2bfloat16(hh - __bfloat162float(hi));
            const int hidx = b * H_ + j0 + jj;
            dsthi[hidx] = hi; dstlo[hidx] = lo;
            const size_t ridx = ((size_t)(b * T_ + t)) * H_ + j0 + jj;
            g_r_hi[ridx] = hi; g_r_lo[ridx] = lo;
            if (t == T_ - 1) {
                out[OUT_HT_OFF + hidx] = hh;
                out[OUT_CT_OFF + hidx] = cc;
            }
        }
        grid_barrier();
    }
}

// ---------------- heads: 14 dots per row of g_sh ----------------
__global__ __launch_bounds__(256) void heads_kernel(
    const float* __restrict__ w_att_s, const float* __restrict__ w_att_r,
    const float* __restrict__ W_state, const float* __restrict__ W_reward)
{
    const int warp = (blockIdx.x * blockDim.x + threadIdx.x) >> 5;
    const int lane = threadIdx.x & 31;
    if (warp >= BT) return;
    const float* rowp = g_sh + (size_t)warp * H_;

    float4 f[8];
#pragma unroll
    for (int i = 0; i < 8; i++)
        f[i] = *reinterpret_cast<const float4*>(rowp + lane * 32 + i * 4);

    float out[14];
#pragma unroll
    for (int fi = 0; fi < 14; fi++) {
        const float* wv = (fi == 0) ? w_att_s
                        : (fi == 1) ? w_att_r
                        : (fi < 13) ? (W_state + (fi - 2) * H_)
                        : W_reward;
        float s = 0.f;
#pragma unroll
        for (int i = 0; i < 8; i++) {
            const float4 w = *reinterpret_cast<const float4*>(wv + lane * 32 + i * 4);
            s += f[i].x * w.x + f[i].y * w.y + f[i].z * w.z + f[i].w * w.w;
        }
#pragma unroll
        for (int o = 16; o; o >>= 1) s += __shfl_xor_sync(0xffffffffu, s, o);
        out[fi] = s;
    }
    if (lane == 0) {
#pragma unroll
        for (int fi = 0; fi < 14; fi++)
            g_proj[(size_t)warp * 16 + fi] = out[fi];
    }
}

// ---------------- causal prefix-softmax scan ----------------
__global__ void scan_kernel(const float* __restrict__ b_state,
                            const float* __restrict__ b_reward,
                            float* __restrict__ out)
{
    const int b = blockIdx.x;
    const int w = threadIdx.x >> 5, lane = threadIdx.x & 31;
    const float* pbase = g_proj + (size_t)b * T_ * 16;

    if (w == 0) {
        float num = 0.f, den = 0.f, m = -INFINITY;
        const float bs = (lane < F_) ? b_state[lane] : 0.f;
        for (int t = 0; t < T_; t++) {
            const float* p = pbase + t * 16;
            const float l = p[0];
            const float v = (lane < F_) ? p[2 + lane] : 0.f;
            const float nm = fmaxf(m, l);
            const float sc = __expf(m - nm);
            const float e  = __expf(l - nm);
            den = den * sc + e;
            num = num * sc + e * v;
            m = nm;
            if (lane < F_)
                out[OUT_STATE_OFF + (size_t)(b * T_ + t) * F_ + lane] = num / den + bs;
        }
    } else if (w == 1) {
        float num = 0.f, den = 0.f, m = -INFINITY;
        const float br = b_reward[0];
        for (int t = 0; t < T_; t++) {
            const float* p = pbase + t * 16;
            const float l = p[1];
            const float v = p[13];
            const float nm = fmaxf(m, l);
            const float sc = __expf(m - nm);
            const float e  = __expf(l - nm);
            den = den * sc + e;
            num = num * sc + e * v;
            m = nm;
            if (lane == 0)
                out[OUT_REWARD_OFF + b * T_ + t] = num / den + br;
        }
    }
}

// ---------------- launch ----------------
extern "C" void kernel_launch(void* const* d_in, const int* in_sizes, int n_in,
                              void* d_out, int out_size)
{
    const float* x        = (const float*)d_in[0];
    const float* h0       = (const float*)d_in[2];
    const float* c0       = (const float*)d_in[3];
    const float* W_ih     = (const float*)d_in[4];
    const float* W_hh     = (const float*)d_in[5];
    const float* b_ih     = (const float*)d_in[6];
    const float* b_hh     = (const float*)d_in[7];
    const float* W_sh     = (const float*)d_in[8];
    const float* b_sh     = (const float*)d_in[9];
    const float* w_att_s  = (const float*)d_in[10];
    const float* w_att_r  = (const float*)d_in[12];
    const float* W_state  = (const float*)d_in[14];
    const float* b_state  = (const float*)d_in[15];
    const float* W_reward = (const float*)d_in[16];
    const float* b_reward = (const float*)d_in[17];
    float* out = (float*)d_out;

    float *Z, *sh;
    __nv_bfloat16 *xh, *xl, *rh, *rl, *wihh, *wihl, *whhh, *whhl, *wshh, *wshl, *hbh, *hbl;
    cudaGetSymbolAddress((void**)&Z,    g_Z);
    cudaGetSymbolAddress((void**)&sh,   g_sh);
    cudaGetSymbolAddress((void**)&xh,   g_x_hi);   cudaGetSymbolAddress((void**)&xl,   g_x_lo);
    cudaGetSymbolAddress((void**)&rh,   g_r_hi);   cudaGetSymbolAddress((void**)&rl,   g_r_lo);
    cudaGetSymbolAddress((void**)&wihh, g_wih_hi); cudaGetSymbolAddress((void**)&wihl, g_wih_lo);
    cudaGetSymbolAddress((void**)&whhh, g_whh_hi); cudaGetSymbolAddress((void**)&whhl, g_whh_lo);
    cudaGetSymbolAddress((void**)&wshh, g_wsh_hi); cudaGetSymbolAddress((void**)&wshl, g_wsh_lo);
    cudaGetSymbolAddress((void**)&hbh,  g_hb_hi);  cudaGetSymbolAddress((void**)&hbl,  g_hb_lo);

    cudaFuncSetAttribute(hgemm_tn, cudaFuncAttributeMaxDynamicSharedMemorySize, GEMM_SMEM);
    cudaFuncSetAttribute(lstm_mma_kernel, cudaFuncAttributeMaxDynamicSharedMemorySize, LSTM_SMEM);

    // splits
    split_kernel<<<(BT * I_) / 256, 256>>>(x, xh, xl, BT * I_);
    split_kernel<<<(G4 * I_) / 256, 256>>>(W_ih, wihh, wihl, G4 * I_);
    split_kernel<<<(G4 * H_) / 256, 256>>>(W_hh, whhh, whhl, G4 * H_);
    split_kernel<<<(H_ * H_) / 256, 256>>>(W_sh, wshh, wshl, H_ * H_);
    split_kernel<<<(B_ * H_) / 256, 256>>>(h0, hbh, hbl, B_ * H_);   // -> g_hb_*[0]

    // Z = x @ W_ih^T + (b_ih + b_hh)   [32768, 4096], K=256
    hgemm_tn<<<dim3(G4 / 128, BT / 128), 256, GEMM_SMEM>>>(
        xh, xl, wihh, wihl, b_ih, b_hh, Z, BT, G4, I_);

    // LSTM recurrence (HMMA)
    init_bar_kernel<<<1, 1>>>();
    lstm_mma_kernel<<<RNC, 256, LSTM_SMEM>>>(c0, out);

    // shared = r @ W_sh^T + b_sh   [32768, 1024], K=1024
    hgemm_tn<<<dim3(H_ / 128, BT / 128), 256, GEMM_SMEM>>>(
        rh, rl, wshh, wshl, b_sh, nullptr, sh, BT, H_, H_);

    // heads + scans
    heads_kernel<<<BT / 8, 256>>>(w_att_s, w_att_r, W_state, W_reward);
    scan_kernel<<<B_, 64>>>(b_state, b_reward, out);
}

// round 10
// speedup vs baseline: 3.1403x; 1.0779x over previous
#include <cuda_runtime.h>
#include <cuda_bf16.h>
#include <cstdint>
#include <math.h>

#define B_   64
#define T_   512
#define I_   256
#define H_   1024
#define F_   11
#define BT   (B_ * T_)
#define G4   (4 * H_)

#define OUT_STATE_OFF  0
#define OUT_REWARD_OFF (BT * F_)
#define OUT_HT_OFF     (OUT_REWARD_OFF + BT)
#define OUT_CT_OFF     (OUT_HT_OFF + B_ * H_)

// ---------------- scratch globals ----------------
__device__ float g_Z[BT * G4];
__device__ float g_sh[BT * H_];
__device__ float g_proj[BT * 16];
__device__ __align__(16) __nv_bfloat16 g_x_hi[BT * I_],  g_x_lo[BT * I_];
__device__ __align__(16) __nv_bfloat16 g_r_hi[BT * H_],  g_r_lo[BT * H_];
__device__ __align__(16) __nv_bfloat16 g_wih_hi[G4 * I_], g_wih_lo[G4 * I_];
__device__ __align__(16) __nv_bfloat16 g_whh_hi[G4 * H_], g_whh_lo[G4 * H_];
__device__ __align__(16) __nv_bfloat16 g_wsh_hi[H_ * H_], g_wsh_lo[H_ * H_];
__device__ __align__(16) __nv_bfloat16 g_hb_hi[2][B_ * H_], g_hb_lo[2][B_ * H_];
// dataflow flags: g_prod[t][c] = #CTAs (of 16) that wrote h(t) chunk c; g_cons[t] = #CTAs done reading h(t)
__device__ int g_prod[T_ + 1][8];
__device__ int g_cons[T_];

// ---------------- helpers ----------------
__device__ __forceinline__ uint32_t smem_u32(const void* p) {
    uint32_t a;
    asm("{ .reg .u64 t; cvta.to.shared.u64 t, %1; cvt.u32.u64 %0, t; }" : "=r"(a) : "l"(p));
    return a;
}
__device__ __forceinline__ void ldmx4(uint32_t* r, uint32_t addr) {
    asm volatile("ldmatrix.sync.aligned.m8n8.x4.shared.b16 {%0,%1,%2,%3}, [%4];"
        : "=r"(r[0]), "=r"(r[1]), "=r"(r[2]), "=r"(r[3]) : "r"(addr));
}
__device__ __forceinline__ void mma_bf16(float* d, const uint32_t* a, uint32_t b0, uint32_t b1) {
    asm volatile("mma.sync.aligned.m16n8k16.row.col.f32.bf16.bf16.f32 "
        "{%0,%1,%2,%3}, {%4,%5,%6,%7}, {%8,%9}, {%0,%1,%2,%3};"
        : "+f"(d[0]), "+f"(d[1]), "+f"(d[2]), "+f"(d[3])
        : "r"(a[0]), "r"(a[1]), "r"(a[2]), "r"(a[3]), "r"(b0), "r"(b1));
}
__device__ __forceinline__ void cp16(uint32_t dst, const void* src) {
    asm volatile("cp.async.cg.shared.global [%0], [%1], 16;" :: "r"(dst), "l"(src));
}
__device__ __forceinline__ void cp_commit() { asm volatile("cp.async.commit_group;" ::: "memory"); }
__device__ __forceinline__ void cp_wait1()  { asm volatile("cp.async.wait_group 1;" ::: "memory"); }
__device__ __forceinline__ void cp_wait0()  { asm volatile("cp.async.wait_group 0;" ::: "memory"); }

__device__ __forceinline__ float sigf(float x) {
    return __fdividef(1.f, 1.f + __expf(-x));
}
__device__ __forceinline__ float tanhf_fast(float x) {
    // 1 - 2/(e^{2x}+1): overflow-safe (+inf -> 1, 0 -> -1)
    return 1.f - __fdividef(2.f, __expf(2.f * x) + 1.f);
}

// ---------------- flag init ----------------
__global__ void init_flags_kernel() {
    int i = blockIdx.x * blockDim.x + threadIdx.x;
    if (i < (T_ + 1) * 8) (&g_prod[0][0])[i] = (i < 8) ? 16 : 0;  // h(0) ready
    if (i < T_) g_cons[i] = 0;
}

// ---------------- fp32 -> bf16 hi/lo split ----------------
__global__ __launch_bounds__(256) void split_kernel(
    const float* __restrict__ src, __nv_bfloat16* __restrict__ hi,
    __nv_bfloat16* __restrict__ lo, int n)
{
    int i = blockIdx.x * blockDim.x + threadIdx.x;
    if (i >= n) return;
    float v = src[i];
    __nv_bfloat16 h = __float2bfloat16(v);
    hi[i] = h;
    lo[i] = __float2bfloat16(v - __bfloat162float(h));
}

// ---------------- bf16 split-precision GEMM (unchanged, passing) ----------------
#define GS_STRIDE_B 80
#define GS_ABUF     10240
#define GS_BOFF     20480
#define GS_BUF      40960
#define GEMM_SMEM   81920

__global__ __launch_bounds__(256) void hgemm_tn(
    const __nv_bfloat16* __restrict__ Ahi, const __nv_bfloat16* __restrict__ Alo,
    const __nv_bfloat16* __restrict__ Whi, const __nv_bfloat16* __restrict__ Wlo,
    const float* __restrict__ bias1, const float* __restrict__ bias2,
    float* __restrict__ C, int M, int N, int K)
{
    extern __shared__ char smg[];
    const uint32_t sb = smem_u32(smg);
    const int tid = threadIdx.x, lane = tid & 31, wid = tid >> 5;
    const int wm = wid >> 2, wn = wid & 3;
    const int m0 = blockIdx.y * 128, n0 = blockIdx.x * 128;

    float acc[4][4][4];
#pragma unroll
    for (int a = 0; a < 4; a++)
#pragma unroll
        for (int b = 0; b < 4; b++)
#pragma unroll
            for (int c = 0; c < 4; c++) acc[a][b][c] = 0.f;

    const int mrow_ld = lane & 15, kA = (lane >> 4) * 8;
    const int nrow_ld = (lane & 7) + ((lane >> 4) << 3), kB = ((lane >> 3) & 1) * 8;
    const int crow = tid >> 1, cd = tid & 1;
    const __nv_bfloat16* As = cd ? Alo : Ahi;
    const __nv_bfloat16* Bs = cd ? Wlo : Whi;
    const int nk = K / 32;

    {
        uint32_t ab = sb + cd * GS_ABUF;
        uint32_t bb = sb + GS_BOFF + cd * GS_ABUF;
#pragma unroll
        for (int s = 0; s < 4; s++) {
            cp16(ab + crow * GS_STRIDE_B + s * 16, (const char*)(As + (size_t)(m0 + crow) * K) + s * 16);
            cp16(bb + crow * GS_STRIDE_B + s * 16, (const char*)(Bs + (size_t)(n0 + crow) * K) + s * 16);
        }
        cp_commit();
    }

    for (int kk = 0; kk < nk; kk++) {
        if (kk + 1 < nk) {
            const int k0 = (kk + 1) * 32;
            uint32_t bufb = ((kk + 1) & 1) * GS_BUF;
            uint32_t ab = sb + bufb + cd * GS_ABUF;
            uint32_t bb = sb + bufb + GS_BOFF + cd * GS_ABUF;
#pragma unroll
            for (int s = 0; s < 4; s++) {
                cp16(ab + crow * GS_STRIDE_B + s * 16, (const char*)(As + (size_t)(m0 + crow) * K + k0) + s * 16);
                cp16(bb + crow * GS_STRIDE_B + s * 16, (const char*)(Bs + (size_t)(n0 + crow) * K + k0) + s * 16);
            }
            cp_commit();
            cp_wait1();
        } else {
            cp_wait0();
        }
        __syncthreads();

        const uint32_t bufb = sb + (kk & 1) * GS_BUF;
#pragma unroll
        for (int ks = 0; ks < 2; ks++) {
            uint32_t ahi[4][4], alo[4][4], bhi[2][4], blo[2][4];
#pragma unroll
            for (int mt = 0; mt < 4; mt++) {
                uint32_t ra = bufb + (wm * 64 + mt * 16 + mrow_ld) * GS_STRIDE_B + (ks * 16 + kA) * 2;
                ldmx4(ahi[mt], ra);
                ldmx4(alo[mt], ra + GS_ABUF);
            }
#pragma unroll
            for (int nb = 0; nb < 2; nb++) {
                uint32_t rb = bufb + GS_BOFF + (wn * 32 + nb * 16 + nrow_ld) * GS_STRIDE_B + (ks * 16 + kB) * 2;
                ldmx4(bhi[nb], rb);
                ldmx4(blo[nb], rb + GS_ABUF);
            }
#pragma unroll
            for (int mt = 0; mt < 4; mt++)
#pragma unroll
                for (int nt = 0; nt < 4; nt++) {
                    const int nb = nt >> 1, hf = (nt & 1) * 2;
                    mma_bf16(acc[mt][nt], ahi[mt], bhi[nb][hf], bhi[nb][hf + 1]);
                    mma_bf16(acc[mt][nt], ahi[mt], blo[nb][hf], blo[nb][hf + 1]);
                    mma_bf16(acc[mt][nt], alo[mt], bhi[nb][hf], bhi[nb][hf + 1]);
                }
        }
        __syncthreads();
    }

    const int g = lane >> 2, tq = lane & 3;
#pragma unroll
    for (int mt = 0; mt < 4; mt++)
#pragma unroll
        for (int nt = 0; nt < 4; nt++) {
            const int row = m0 + wm * 64 + mt * 16 + g;
            const int col = n0 + wn * 32 + nt * 8 + tq * 2;
            float b0 = 0.f, b1 = 0.f;
            if (bias1) { b0 += bias1[col]; b1 += bias1[col + 1]; }
            if (bias2) { b0 += bias2[col]; b1 += bias2[col + 1]; }
            C[(size_t)row * N + col]           = acc[mt][nt][0] + b0;
            C[(size_t)row * N + col + 1]       = acc[mt][nt][1] + b1;
            C[(size_t)(row + 8) * N + col]     = acc[mt][nt][2] + b0;
            C[(size_t)(row + 8) * N + col + 1] = acc[mt][nt][3] + b1;
        }
}

// ---------------- persistent HMMA LSTM recurrence (flag-pipelined) ----------------
// 128 CTAs x 256 threads. CTA bid owns gate rows {g*1024 + bid*8 + jj}.
// W slice (hi+lo) resident in smem; h streamed hi/lo in 8 K-chunks of 128.
// Synchronization: per-chunk producer flags + per-step consumer counts (no grid barrier).
#define RNC 128
#define RS_WHI   0
#define RS_WLO   66048          // 32 rows * 2064B
#define RS_H     132096         // 2 bufs * 34816 (hi 17408 | lo 17408)
#define RS_HBUF  34816
#define RS_HLO   17408
#define RS_ZSM   201728         // 32*66*4 = 8448
#define LSTM_SMEM 210176

__global__ __launch_bounds__(256, 1) void lstm_mma_kernel(const float* __restrict__ c0,
                                                          float* __restrict__ out)
{
    extern __shared__ char sml[];
    const uint32_t sb = smem_u32(sml);
    float* zsm = reinterpret_cast<float*>(sml + RS_ZSM);

    const int tid = threadIdx.x, bid = blockIdx.x;
    const int lane = tid & 31, wid = tid >> 5;
    const int wm = wid >> 2, wn = wid & 3;
    const int j0 = bid * 8;
    const int my_chunk = bid >> 4;

    // one-time: W slice (32 rows x 1024) hi+lo into smem
#pragma unroll
    for (int u = 0; u < 16; u++) {
        const int idx = tid + u * 256;
        const int r = idx >> 7, seg = idx & 127;
        const int grow = (r >> 3) * H_ + j0 + (r & 7);
        cp16(sb + RS_WHI + r * 2064 + seg * 16, (const char*)(g_whh_hi + (size_t)grow * H_) + seg * 16);
        cp16(sb + RS_WLO + r * 2064 + seg * 16, (const char*)(g_whh_lo + (size_t)grow * H_) + seg * 16);
    }
    cp_commit(); cp_wait0(); __syncthreads();

    float creg[2];
#pragma unroll
    for (int r = 0; r < 2; r++) {
        const int e = tid + r * 256;
        creg[r] = c0[(e >> 3) * H_ + j0 + (e & 7)];
    }

    const int mrow_ld = lane & 15, kA = (lane >> 4) * 8;
    const int nrow_ld = (lane & 7) + ((lane >> 4) << 3), kB = ((lane >> 3) & 1) * 8;

    for (int t = 0; t < T_; t++) {
        const char* hhi = (const char*)g_hb_hi[t & 1];
        const char* hlo = (const char*)g_hb_lo[t & 1];

        // early z loads (independent of h; DRAM latency hidden under staging+MMA)
        float zr[2][4];
#pragma unroll
        for (int r = 0; r < 2; r++) {
            const int e = tid + r * 256;
            const size_t zoff = ((size_t)((e >> 3) * T_ + t)) * G4 + j0 + (e & 7);
#pragma unroll
            for (int gg = 0; gg < 4; gg++) zr[r][gg] = g_Z[zoff + (size_t)gg * H_];
        }

        float acc[2][4] = {{0.f,0.f,0.f,0.f},{0.f,0.f,0.f,0.f}};

        // stage chunk 0 (wait for its 16 producers)
        {
            volatile int* f = &g_prod[t][0];
            while (*f < 16) { }
#pragma unroll
            for (int i = 0; i < 8; i++) {
                const int u = tid + i * 256, d = u >> 10, v = u & 1023;
                const int b = v >> 4, s = v & 15;
                cp16(sb + RS_H + d * RS_HLO + b * 272 + s * 16,
                     (d ? hlo : hhi) + b * 2048 + s * 16);
            }
            cp_commit();
        }

        for (int c = 0; c < 8; c++) {
            if (c + 1 < 8) {
                volatile int* f = &g_prod[t][c + 1];
                while (*f < 16) { }
                const uint32_t hb = sb + RS_H + ((c + 1) & 1) * RS_HBUF;
#pragma unroll
                for (int i = 0; i < 8; i++) {
                    const int u = tid + i * 256, d = u >> 10, v = u & 1023;
                    const int b = v >> 4, s = v & 15;
                    cp16(hb + d * RS_HLO + b * 272 + s * 16,
                         (d ? hlo : hhi) + b * 2048 + (c + 1) * 256 + s * 16);
                }
                cp_commit();
                cp_wait1();
            } else {
                cp_wait0();
                if (tid == 0) atomicAdd(&g_cons[t], 1);   // done reading h(t)
            }
            __syncthreads();

            const uint32_t hb = sb + RS_H + (c & 1) * RS_HBUF;
#pragma unroll
            for (int ks = 0; ks < 8; ks++) {
                uint32_t ahr[4], alr[4], bhr[4], blr[4];
                const uint32_t ra = sb + RS_WHI + (wm * 16 + mrow_ld) * 2064 + (c * 128 + ks * 16 + kA) * 2;
                ldmx4(ahr, ra);
                ldmx4(alr, ra + (RS_WLO - RS_WHI));
                const uint32_t rb = hb + (wn * 16 + nrow_ld) * 272 + (ks * 16 + kB) * 2;
                ldmx4(bhr, rb);
                ldmx4(blr, rb + RS_HLO);
#pragma unroll
                for (int ti = 0; ti < 2; ti++) {
                    mma_bf16(acc[ti], ahr, bhr[ti * 2], bhr[ti * 2 + 1]);
                    mma_bf16(acc[ti], ahr, blr[ti * 2], blr[ti * 2 + 1]);
                    mma_bf16(acc[ti], alr, bhr[ti * 2], bhr[ti * 2 + 1]);
                }
            }
            __syncthreads();
        }

        // frags -> zsm [row = gate*8+jj][batch]
        {
            const int g = lane >> 2, tq = lane & 3;
#pragma unroll
            for (int ti = 0; ti < 2; ti++) {
                const int col = wn * 16 + ti * 8 + tq * 2;
                zsm[(wm * 16 + g) * 66 + col]         = acc[ti][0];
                zsm[(wm * 16 + g) * 66 + col + 1]     = acc[ti][1];
                zsm[(wm * 16 + g + 8) * 66 + col]     = acc[ti][2];
                zsm[(wm * 16 + g + 8) * 66 + col + 1] = acc[ti][3];
            }
        }
        __syncthreads();

        // WAR guard: before overwriting h buffer (parity of t+1 == t-1),
        // all CTAs must have finished reading h(t-1).
        if (t >= 1) {
            volatile int* f = &g_cons[t - 1];
            while (*f < RNC) { }
        }

        // gates
        __nv_bfloat16* __restrict__ dsthi = g_hb_hi[(t + 1) & 1];
        __nv_bfloat16* __restrict__ dstlo = g_hb_lo[(t + 1) & 1];
#pragma unroll
        for (int r = 0; r < 2; r++) {
            const int e = tid + r * 256;
            const int b = e >> 3, jj = e & 7;
            const float zi = zsm[(0 * 8 + jj) * 66 + b] + zr[r][0];
            const float zf = zsm[(1 * 8 + jj) * 66 + b] + zr[r][1];
            const float zg = zsm[(2 * 8 + jj) * 66 + b] + zr[r][2];
            const float zo = zsm[(3 * 8 + jj) * 66 + b] + zr[r][3];
            const float cc = sigf(zf) * creg[r] + sigf(zi) * tanhf_fast(zg);
            const float hh = sigf(zo) * tanhf_fast(cc);
            creg[r] = cc;
            const __nv_bfloat16 hi = __float2bfloat16(hh);
            const __nv_bfloat16 lo = __float2bfloat16(hh - __bfloat162float(hi));
            const int hidx = b * H_ + j0 + jj;
            dsthi[hidx] = hi; dstlo[hidx] = lo;
            const size_t ridx = ((size_t)(b * T_ + t)) * H_ + j0 + jj;
            g_r_hi[ridx] = hi; g_r_lo[ridx] = lo;
            if (t == T_ - 1) {
                out[OUT_HT_OFF + hidx] = hh;
                out[OUT_CT_OFF + hidx] = cc;
            }
        }
        __threadfence();
        __syncthreads();
        if (tid == 0) atomicAdd(&g_prod[t + 1][my_chunk], 1);   // publish h(t+1) chunk
    }
}

// ---------------- heads: 14 dots per row of g_sh ----------------
__global__ __launch_bounds__(256) void heads_kernel(
    const float* __restrict__ w_att_s, const float* __restrict__ w_att_r,
    const float* __restrict__ W_state, const float* __restrict__ W_reward)
{
    const int warp = (blockIdx.x * blockDim.x + threadIdx.x) >> 5;
    const int lane = threadIdx.x & 31;
    if (warp >= BT) return;
    const float* rowp = g_sh + (size_t)warp * H_;

    float4 f[8];
#pragma unroll
    for (int i = 0; i < 8; i++)
        f[i] = *reinterpret_cast<const float4*>(rowp + lane * 32 + i * 4);

    float out[14];
#pragma unroll
    for (int fi = 0; fi < 14; fi++) {
        const float* wv = (fi == 0) ? w_att_s
                        : (fi == 1) ? w_att_r
                        : (fi < 13) ? (W_state + (fi - 2) * H_)
                        : W_reward;
        float s = 0.f;
#pragma unroll
        for (int i = 0; i < 8; i++) {
            const float4 w = *reinterpret_cast<const float4*>(wv + lane * 32 + i * 4);
            s += f[i].x * w.x + f[i].y * w.y + f[i].z * w.z + f[i].w * w.w;
        }
#pragma unroll
        for (int o = 16; o; o >>= 1) s += __shfl_xor_sync(0xffffffffu, s, o);
        out[fi] = s;
    }
    if (lane == 0) {
#pragma unroll
        for (int fi = 0; fi < 14; fi++)
            g_proj[(size_t)warp * 16 + fi] = out[fi];
    }
}

// ---------------- causal prefix-softmax scan ----------------
__global__ void scan_kernel(const float* __restrict__ b_state,
                            const float* __restrict__ b_reward,
                            float* __restrict__ out)
{
    const int b = blockIdx.x;
    const int w = threadIdx.x >> 5, lane = threadIdx.x & 31;
    const float* pbase = g_proj + (size_t)b * T_ * 16;

    if (w == 0) {
        float num = 0.f, den = 0.f, m = -INFINITY;
        const float bs = (lane < F_) ? b_state[lane] : 0.f;
        for (int t = 0; t < T_; t++) {
            const float* p = pbase + t * 16;
            const float l = p[0];
            const float v = (lane < F_) ? p[2 + lane] : 0.f;
            const float nm = fmaxf(m, l);
            const float sc = __expf(m - nm);
            const float e  = __expf(l - nm);
            den = den * sc + e;
            num = num * sc + e * v;
            m = nm;
            if (lane < F_)
                out[OUT_STATE_OFF + (size_t)(b * T_ + t) * F_ + lane] = num / den + bs;
        }
    } else if (w == 1) {
        float num = 0.f, den = 0.f, m = -INFINITY;
        const float br = b_reward[0];
        for (int t = 0; t < T_; t++) {
            const float* p = pbase + t * 16;
            const float l = p[1];
            const float v = p[13];
            const float nm = fmaxf(m, l);
            const float sc = __expf(m - nm);
            const float e  = __expf(l - nm);
            den = den * sc + e;
            num = num * sc + e * v;
            m = nm;
            if (lane == 0)
                out[OUT_REWARD_OFF + b * T_ + t] = num / den + br;
        }
    }
}

// ---------------- launch ----------------
extern "C" void kernel_launch(void* const* d_in, const int* in_sizes, int n_in,
                              void* d_out, int out_size)
{
    const float* x        = (const float*)d_in[0];
    const float* h0       = (const float*)d_in[2];
    const float* c0       = (const float*)d_in[3];
    const float* W_ih     = (const float*)d_in[4];
    const float* W_hh     = (const float*)d_in[5];
    const float* b_ih     = (const float*)d_in[6];
    const float* b_hh     = (const float*)d_in[7];
    const float* W_sh     = (const float*)d_in[8];
    const float* b_sh     = (const float*)d_in[9];
    const float* w_att_s  = (const float*)d_in[10];
    const float* w_att_r  = (const float*)d_in[12];
    const float* W_state  = (const float*)d_in[14];
    const float* b_state  = (const float*)d_in[15];
    const float* W_reward = (const float*)d_in[16];
    const float* b_reward = (const float*)d_in[17];
    float* out = (float*)d_out;

    float *Z, *sh;
    __nv_bfloat16 *xh, *xl, *rh, *rl, *wihh, *wihl, *whhh, *whhl, *wshh, *wshl, *hbh, *hbl;
    cudaGetSymbolAddress((void**)&Z,    g_Z);
    cudaGetSymbolAddress((void**)&sh,   g_sh);
    cudaGetSymbolAddress((void**)&xh,   g_x_hi);   cudaGetSymbolAddress((void**)&xl,   g_x_lo);
    cudaGetSymbolAddress((void**)&rh,   g_r_hi);   cudaGetSymbolAddress((void**)&rl,   g_r_lo);
    cudaGetSymbolAddress((void**)&wihh, g_wih_hi); cudaGetSymbolAddress((void**)&wihl, g_wih_lo);
    cudaGetSymbolAddress((void**)&whhh, g_whh_hi); cudaGetSymbolAddress((void**)&whhl, g_whh_lo);
    cudaGetSymbolAddress((void**)&wshh, g_wsh_hi); cudaGetSymbolAddress((void**)&wshl, g_wsh_lo);
    cudaGetSymbolAddress((void**)&hbh,  g_hb_hi);  cudaGetSymbolAddress((void**)&hbl,  g_hb_lo);

    cudaFuncSetAttribute(hgemm_tn, cudaFuncAttributeMaxDynamicSharedMemorySize, GEMM_SMEM);
    cudaFuncSetAttribute(lstm_mma_kernel, cudaFuncAttributeMaxDynamicSharedMemorySize, LSTM_SMEM);

    // splits + flag init
    split_kernel<<<(BT * I_) / 256, 256>>>(x, xh, xl, BT * I_);
    split_kernel<<<(G4 * I_) / 256, 256>>>(W_ih, wihh, wihl, G4 * I_);
    split_kernel<<<(G4 * H_) / 256, 256>>>(W_hh, whhh, whhl, G4 * H_);
    split_kernel<<<(H_ * H_) / 256, 256>>>(W_sh, wshh, wshl, H_ * H_);
    split_kernel<<<(B_ * H_) / 256, 256>>>(h0, hbh, hbl, B_ * H_);   // -> g_hb_*[0]
    init_flags_kernel<<<17, 256>>>();

    // Z = x @ W_ih^T + (b_ih + b_hh)   [32768, 4096], K=256
    hgemm_tn<<<dim3(G4 / 128, BT / 128), 256, GEMM_SMEM>>>(
        xh, xl, wihh, wihl, b_ih, b_hh, Z, BT, G4, I_);

    // LSTM recurrence (HMMA, dataflow-pipelined)
    lstm_mma_kernel<<<RNC, 256, LSTM_SMEM>>>(c0, out);

    // shared = r @ W_sh^T + b_sh   [32768, 1024], K=1024
    hgemm_tn<<<dim3(H_ / 128, BT / 128), 256, GEMM_SMEM>>>(
        rh, rl, wshh, wshl, b_sh, nullptr, sh, BT, H_, H_);

    // heads + scans
    heads_kernel<<<BT / 8, 256>>>(w_att_s, w_att_r, W_state, W_reward);
    scan_kernel<<<B_, 64>>>(b_state, b_reward, out);
}